// round 7
// baseline (speedup 1.0000x reference)
#include <cuda_runtime.h>

#define HID 512
#define H3  256
#define TB  48          // batch rows per CTA
#define NTHREADS 512
#define RPT 3           // rows per thread = TB / (NTHREADS/32)

__global__ void __launch_bounds__(NTHREADS, 1)
node_rk4_kernel(const float* __restrict__ y0,
                const float* __restrict__ tp,
                const float* __restrict__ W1, const float* __restrict__ b1,
                const float* __restrict__ W2, const float* __restrict__ b2,
                const float* __restrict__ W3, const float* __restrict__ b3,
                const float* __restrict__ W4, const float* __restrict__ b4,
                float* __restrict__ out, int B, int T)
{
    extern __shared__ float sm[];
    float* bufA   = sm;                    // TB*HID
    float* bufB   = sm + TB * HID;         // TB*HID
    float* ycur   = sm + 2 * TB * HID;     // TB*2
    float* ystage = ycur + TB * 2;         // TB*2
    float* ysum   = ystage + TB * 2;       // TB*2

    const int tid  = threadIdx.x;
    const int lane = tid & 31;
    const int r0   = (tid >> 5) * RPT;     // first of my 3 rows
    const int base = blockIdx.x * TB;

    // ---- init state + write t=0 snapshot ----
    if (tid < TB * 2) {
        int r = tid >> 1, c = tid & 1;
        long g = (long)base + r;
        float v = (g < B) ? y0[g * 2 + c] : 0.0f;
        ycur[tid] = v;
        if (g < B) out[g * 2 + c] = v;
    }
    __syncthreads();

    for (int s = 0; s < T - 1; ++s) {
        const float dt = tp[s + 1] - tp[s];

        #pragma unroll 1
        for (int stage = 0; stage < 4; ++stage) {
            const float* yin = (stage == 0) ? ycur : ystage;

            // ================= layer 1: (2 -> 512), out -> bufA =================
            {
                const int c0 = lane * 16;
                float w0c[16], w1c[16], bb[16];
                #pragma unroll
                for (int c = 0; c < 16; ++c) {
                    w0c[c] = W1[c0 + c];
                    w1c[c] = W1[HID + c0 + c];
                    bb[c]  = b1[c0 + c];
                }
                #pragma unroll
                for (int i = 0; i < RPT; ++i) {
                    const int r = r0 + i;
                    const float a0 = yin[r * 2 + 0];
                    const float a1 = yin[r * 2 + 1];
                    #pragma unroll
                    for (int c = 0; c < 16; ++c) {
                        float acc = fmaf(a0, w0c[c], fmaf(a1, w1c[c], bb[c]));
                        bufA[r * HID + c0 + c] = tanhf(acc);
                    }
                }
            }
            __syncthreads();

            // ================= layer 2: (512 -> 512), bufA -> bufB ==============
            {
                const int c0 = lane * 16;
                float acc[RPT][16];
                #pragma unroll
                for (int i = 0; i < RPT; ++i)
                    #pragma unroll
                    for (int c = 0; c < 16; ++c) acc[i][c] = 0.0f;

                const float* A0 = bufA + r0 * HID;
                #pragma unroll 4
                for (int k = 0; k < HID; ++k) {
                    const float4 w0 = *(const float4*)(W2 + (size_t)k * HID + c0);
                    const float4 w1 = *(const float4*)(W2 + (size_t)k * HID + c0 + 4);
                    const float4 w2 = *(const float4*)(W2 + (size_t)k * HID + c0 + 8);
                    const float4 w3 = *(const float4*)(W2 + (size_t)k * HID + c0 + 12);
                    float a[RPT];
                    #pragma unroll
                    for (int i = 0; i < RPT; ++i) a[i] = A0[i * HID + k];
                    #pragma unroll
                    for (int i = 0; i < RPT; ++i) {
                        acc[i][0]  = fmaf(a[i], w0.x, acc[i][0]);
                        acc[i][1]  = fmaf(a[i], w0.y, acc[i][1]);
                        acc[i][2]  = fmaf(a[i], w0.z, acc[i][2]);
                        acc[i][3]  = fmaf(a[i], w0.w, acc[i][3]);
                        acc[i][4]  = fmaf(a[i], w1.x, acc[i][4]);
                        acc[i][5]  = fmaf(a[i], w1.y, acc[i][5]);
                        acc[i][6]  = fmaf(a[i], w1.z, acc[i][6]);
                        acc[i][7]  = fmaf(a[i], w1.w, acc[i][7]);
                        acc[i][8]  = fmaf(a[i], w2.x, acc[i][8]);
                        acc[i][9]  = fmaf(a[i], w2.y, acc[i][9]);
                        acc[i][10] = fmaf(a[i], w2.z, acc[i][10]);
                        acc[i][11] = fmaf(a[i], w2.w, acc[i][11]);
                        acc[i][12] = fmaf(a[i], w3.x, acc[i][12]);
                        acc[i][13] = fmaf(a[i], w3.y, acc[i][13]);
                        acc[i][14] = fmaf(a[i], w3.z, acc[i][14]);
                        acc[i][15] = fmaf(a[i], w3.w, acc[i][15]);
                    }
                }
                #pragma unroll
                for (int i = 0; i < RPT; ++i) {
                    const int r = r0 + i;
                    #pragma unroll
                    for (int c = 0; c < 16; ++c)
                        bufB[r * HID + c0 + c] = tanhf(acc[i][c] + b2[c0 + c]);
                }
            }
            __syncthreads();

            // ================= layer 3: (512 -> 256), bufB -> bufA ==============
            {
                const int c0 = lane * 8;
                float acc[RPT][8];
                #pragma unroll
                for (int i = 0; i < RPT; ++i)
                    #pragma unroll
                    for (int c = 0; c < 8; ++c) acc[i][c] = 0.0f;

                const float* A0 = bufB + r0 * HID;
                #pragma unroll 4
                for (int k = 0; k < HID; ++k) {
                    const float4 w0 = *(const float4*)(W3 + (size_t)k * H3 + c0);
                    const float4 w1 = *(const float4*)(W3 + (size_t)k * H3 + c0 + 4);
                    float a[RPT];
                    #pragma unroll
                    for (int i = 0; i < RPT; ++i) a[i] = A0[i * HID + k];
                    #pragma unroll
                    for (int i = 0; i < RPT; ++i) {
                        acc[i][0] = fmaf(a[i], w0.x, acc[i][0]);
                        acc[i][1] = fmaf(a[i], w0.y, acc[i][1]);
                        acc[i][2] = fmaf(a[i], w0.z, acc[i][2]);
                        acc[i][3] = fmaf(a[i], w0.w, acc[i][3]);
                        acc[i][4] = fmaf(a[i], w1.x, acc[i][4]);
                        acc[i][5] = fmaf(a[i], w1.y, acc[i][5]);
                        acc[i][6] = fmaf(a[i], w1.z, acc[i][6]);
                        acc[i][7] = fmaf(a[i], w1.w, acc[i][7]);
                    }
                }
                #pragma unroll
                for (int i = 0; i < RPT; ++i) {
                    const int r = r0 + i;
                    #pragma unroll
                    for (int c = 0; c < 8; ++c)
                        bufA[r * H3 + c0 + c] = tanhf(acc[i][c] + b3[c0 + c]);
                }
            }
            __syncthreads();

            // ===== layer 4 (256 -> 2) + RK4 stage update (96 threads) ==========
            if (tid < TB * 2) {
                const int r = tid >> 1, comp = tid & 1;
                const float* h = bufA + r * H3;
                float acc = b4[comp];
                #pragma unroll 8
                for (int k = 0; k < H3; ++k)
                    acc = fmaf(h[k], W4[k * 2 + comp], acc);

                const float f = acc;
                if (stage == 0) {
                    ysum[tid]   = f;
                    ystage[tid] = fmaf(0.5f * dt, f, ycur[tid]);
                } else if (stage == 1) {
                    ysum[tid]  += 2.0f * f;
                    ystage[tid] = fmaf(0.5f * dt, f, ycur[tid]);
                } else if (stage == 2) {
                    ysum[tid]  += 2.0f * f;
                    ystage[tid] = fmaf(dt, f, ycur[tid]);
                } else {
                    const float yn = fmaf(dt * (1.0f / 6.0f), ysum[tid] + f, ycur[tid]);
                    ycur[tid] = yn;
                    long g = (long)base + r;
                    if (g < B)
                        out[(size_t)(s + 1) * B * 2 + g * 2 + comp] = yn;
                }
            }
            __syncthreads();
        }
    }
}

extern "C" void kernel_launch(void* const* d_in, const int* in_sizes, int n_in,
                              void* d_out, int out_size) {
    const float* y0 = (const float*)d_in[0];
    const float* tp = (const float*)d_in[1];
    const float* W1 = (const float*)d_in[2];
    const float* b1 = (const float*)d_in[3];
    const float* W2 = (const float*)d_in[4];
    const float* b2 = (const float*)d_in[5];
    const float* W3 = (const float*)d_in[6];
    const float* b3 = (const float*)d_in[7];
    const float* W4 = (const float*)d_in[8];
    const float* b4 = (const float*)d_in[9];
    float* out = (float*)d_out;

    const int B = in_sizes[0] / 2;   // 65536
    const int T = in_sizes[1];       // 100

    const size_t smem = (size_t)(2 * TB * HID + 3 * TB * 2) * sizeof(float);
    cudaFuncSetAttribute(node_rk4_kernel,
                         cudaFuncAttributeMaxDynamicSharedMemorySize, (int)smem);

    const int grid = (B + TB - 1) / TB;
    node_rk4_kernel<<<grid, NTHREADS, smem>>>(y0, tp, W1, b1, W2, b2,
                                              W3, b3, W4, b4, out, B, T);
}

// round 8
// speedup vs baseline: 1.0551x; 1.0551x over previous
#include <cuda_runtime.h>

#define HID 512
#define H3  256
#define TB  48          // batch rows per CTA
#define NTHREADS 512
#define RPT 3           // rows per thread = TB / (NTHREADS/32)

__global__ void __launch_bounds__(NTHREADS, 1)
node_rk4_kernel(const float* __restrict__ y0,
                const float* __restrict__ tp,
                const float* __restrict__ W1, const float* __restrict__ b1,
                const float* __restrict__ W2, const float* __restrict__ b2,
                const float* __restrict__ W3, const float* __restrict__ b3,
                const float* __restrict__ W4, const float* __restrict__ b4,
                float* __restrict__ out, int B, int T)
{
    extern __shared__ float sm[];
    float* bufA   = sm;                    // TB*HID
    float* bufB   = sm + TB * HID;         // TB*HID
    float* ycur   = sm + 2 * TB * HID;     // TB*2
    float* ystage = ycur + TB * 2;         // TB*2
    float* ysum   = ystage + TB * 2;       // TB*2

    const int tid  = threadIdx.x;
    const int lane = tid & 31;
    const int r0   = (tid >> 5) * RPT;     // first of my 3 rows
    const int base = blockIdx.x * TB;

    // ---- init state + write t=0 snapshot ----
    if (tid < TB * 2) {
        int r = tid >> 1, c = tid & 1;
        long g = (long)base + r;
        float v = (g < B) ? y0[g * 2 + c] : 0.0f;
        ycur[tid] = v;
        if (g < B) out[g * 2 + c] = v;
    }
    __syncthreads();

    for (int s = 0; s < T - 1; ++s) {
        const float dt = tp[s + 1] - tp[s];

        #pragma unroll 1
        for (int stage = 0; stage < 4; ++stage) {
            const float* yin = (stage == 0) ? ycur : ystage;

            // ================= layer 1: (2 -> 512), out -> bufA =================
            {
                const int c0 = lane * 16;
                float w0c[16], w1c[16], bb[16];
                #pragma unroll
                for (int c = 0; c < 16; ++c) {
                    w0c[c] = W1[c0 + c];
                    w1c[c] = W1[HID + c0 + c];
                    bb[c]  = b1[c0 + c];
                }
                #pragma unroll
                for (int i = 0; i < RPT; ++i) {
                    const int r = r0 + i;
                    const float a0 = yin[r * 2 + 0];
                    const float a1 = yin[r * 2 + 1];
                    #pragma unroll
                    for (int c = 0; c < 16; ++c) {
                        float acc = fmaf(a0, w0c[c], fmaf(a1, w1c[c], bb[c]));
                        bufA[r * HID + c0 + c] = tanhf(acc);
                    }
                }
            }
            __syncthreads();

            // ================= layer 2: (512 -> 512), bufA -> bufB ==============
            {
                const int c0 = lane * 16;
                float acc[RPT][16];
                #pragma unroll
                for (int i = 0; i < RPT; ++i)
                    #pragma unroll
                    for (int c = 0; c < 16; ++c) acc[i][c] = 0.0f;

                const float* A0 = bufA + r0 * HID;
                #pragma unroll 4
                for (int k = 0; k < HID; ++k) {
                    const float4 w0 = *(const float4*)(W2 + (size_t)k * HID + c0);
                    const float4 w1 = *(const float4*)(W2 + (size_t)k * HID + c0 + 4);
                    const float4 w2 = *(const float4*)(W2 + (size_t)k * HID + c0 + 8);
                    const float4 w3 = *(const float4*)(W2 + (size_t)k * HID + c0 + 12);
                    float a[RPT];
                    #pragma unroll
                    for (int i = 0; i < RPT; ++i) a[i] = A0[i * HID + k];
                    #pragma unroll
                    for (int i = 0; i < RPT; ++i) {
                        acc[i][0]  = fmaf(a[i], w0.x, acc[i][0]);
                        acc[i][1]  = fmaf(a[i], w0.y, acc[i][1]);
                        acc[i][2]  = fmaf(a[i], w0.z, acc[i][2]);
                        acc[i][3]  = fmaf(a[i], w0.w, acc[i][3]);
                        acc[i][4]  = fmaf(a[i], w1.x, acc[i][4]);
                        acc[i][5]  = fmaf(a[i], w1.y, acc[i][5]);
                        acc[i][6]  = fmaf(a[i], w1.z, acc[i][6]);
                        acc[i][7]  = fmaf(a[i], w1.w, acc[i][7]);
                        acc[i][8]  = fmaf(a[i], w2.x, acc[i][8]);
                        acc[i][9]  = fmaf(a[i], w2.y, acc[i][9]);
                        acc[i][10] = fmaf(a[i], w2.z, acc[i][10]);
                        acc[i][11] = fmaf(a[i], w2.w, acc[i][11]);
                        acc[i][12] = fmaf(a[i], w3.x, acc[i][12]);
                        acc[i][13] = fmaf(a[i], w3.y, acc[i][13]);
                        acc[i][14] = fmaf(a[i], w3.z, acc[i][14]);
                        acc[i][15] = fmaf(a[i], w3.w, acc[i][15]);
                    }
                }
                #pragma unroll
                for (int i = 0; i < RPT; ++i) {
                    const int r = r0 + i;
                    #pragma unroll
                    for (int c = 0; c < 16; ++c)
                        bufB[r * HID + c0 + c] = tanhf(acc[i][c] + b2[c0 + c]);
                }
            }
            __syncthreads();

            // ================= layer 3: (512 -> 256), bufB -> bufA ==============
            {
                const int c0 = lane * 8;
                float acc[RPT][8];
                #pragma unroll
                for (int i = 0; i < RPT; ++i)
                    #pragma unroll
                    for (int c = 0; c < 8; ++c) acc[i][c] = 0.0f;

                const float* A0 = bufB + r0 * HID;
                #pragma unroll 4
                for (int k = 0; k < HID; ++k) {
                    const float4 w0 = *(const float4*)(W3 + (size_t)k * H3 + c0);
                    const float4 w1 = *(const float4*)(W3 + (size_t)k * H3 + c0 + 4);
                    float a[RPT];
                    #pragma unroll
                    for (int i = 0; i < RPT; ++i) a[i] = A0[i * HID + k];
                    #pragma unroll
                    for (int i = 0; i < RPT; ++i) {
                        acc[i][0] = fmaf(a[i], w0.x, acc[i][0]);
                        acc[i][1] = fmaf(a[i], w0.y, acc[i][1]);
                        acc[i][2] = fmaf(a[i], w0.z, acc[i][2]);
                        acc[i][3] = fmaf(a[i], w0.w, acc[i][3]);
                        acc[i][4] = fmaf(a[i], w1.x, acc[i][4]);
                        acc[i][5] = fmaf(a[i], w1.y, acc[i][5]);
                        acc[i][6] = fmaf(a[i], w1.z, acc[i][6]);
                        acc[i][7] = fmaf(a[i], w1.w, acc[i][7]);
                    }
                }
                #pragma unroll
                for (int i = 0; i < RPT; ++i) {
                    const int r = r0 + i;
                    #pragma unroll
                    for (int c = 0; c < 8; ++c)
                        bufA[r * H3 + c0 + c] = tanhf(acc[i][c] + b3[c0 + c]);
                }
            }
            __syncthreads();

            // ===== layer 4 (256 -> 2) + RK4 stage update (96 threads) ==========
            if (tid < TB * 2) {
                const int r = tid >> 1, comp = tid & 1;
                const float* h = bufA + r * H3;
                float acc = b4[comp];
                #pragma unroll 8
                for (int k = 0; k < H3; ++k)
                    acc = fmaf(h[k], W4[k * 2 + comp], acc);

                const float f = acc;
                if (stage == 0) {
                    ysum[tid]   = f;
                    ystage[tid] = fmaf(0.5f * dt, f, ycur[tid]);
                } else if (stage == 1) {
                    ysum[tid]  += 2.0f * f;
                    ystage[tid] = fmaf(0.5f * dt, f, ycur[tid]);
                } else if (stage == 2) {
                    ysum[tid]  += 2.0f * f;
                    ystage[tid] = fmaf(dt, f, ycur[tid]);
                } else {
                    const float yn = fmaf(dt * (1.0f / 6.0f), ysum[tid] + f, ycur[tid]);
                    ycur[tid] = yn;
                    long g = (long)base + r;
                    if (g < B)
                        out[(size_t)(s + 1) * B * 2 + g * 2 + comp] = yn;
                }
            }
            __syncthreads();
        }
    }
}

extern "C" void kernel_launch(void* const* d_in, const int* in_sizes, int n_in,
                              void* d_out, int out_size) {
    const float* y0 = (const float*)d_in[0];
    const float* tp = (const float*)d_in[1];
    const float* W1 = (const float*)d_in[2];
    const float* b1 = (const float*)d_in[3];
    const float* W2 = (const float*)d_in[4];
    const float* b2 = (const float*)d_in[5];
    const float* W3 = (const float*)d_in[6];
    const float* b3 = (const float*)d_in[7];
    const float* W4 = (const float*)d_in[8];
    const float* b4 = (const float*)d_in[9];
    float* out = (float*)d_out;

    const int B = in_sizes[0] / 2;   // 65536
    const int T = in_sizes[1];       // 100

    const size_t smem = (size_t)(2 * TB * HID + 3 * TB * 2) * sizeof(float);
    cudaFuncSetAttribute(node_rk4_kernel,
                         cudaFuncAttributeMaxDynamicSharedMemorySize, (int)smem);

    const int grid = (B + TB - 1) / TB;
    node_rk4_kernel<<<grid, NTHREADS, smem>>>(y0, tp, W1, b1, W2, b2,
                                              W3, b3, W4, b4, out, B, T);
}

// round 11
// speedup vs baseline: 16.0978x; 15.2566x over previous
#include <cuda_runtime.h>
#include <cuda_fp16.h>
#include <stdint.h>
#include <string.h>

#define NT     512
#define MROWS  128
#define ASTR   1040      // bytes per padded A row (520 halfs)

// Fragment-ordered fp16 weights:
// layout: [nc][slab(128k)][ks(8)][wn(4)][lane(32)][tn(4)][reg(2)][half(2)]
__device__ __align__(16) unsigned char g_WF2[524288];   // W2: nc=4
__device__ __align__(16) unsigned char g_WF3[262144];   // W3: nc=2

// ---------------- smem layout (bytes) ----------------
#define SM_A     0                         // 128*1040 = 133120
#define SM_SLAB  133120                    // 2 x 32768
#define SM_W1    (SM_SLAB + 65536)         // 1024 f32
#define SM_B1    (SM_W1 + 4096)            // 512 f32
#define SM_B2    (SM_B1 + 2048)            // 512 f32
#define SM_B3    (SM_B2 + 2048)            // 256 f32
#define SM_W4    (SM_B3 + 1024)            // 512 f32
#define SM_B4    (SM_W4 + 2048)            // 2 f32 (+pad)
#define SM_RED   (SM_B4 + 16)              // 128*4*2 f32
#define SM_YC    (SM_RED + 4096)
#define SM_YS    (SM_YC + 1024)
#define SM_YSUM  (SM_YS + 1024)
#define SM_TOTAL (SM_YSUM + 1024)          // 217104

static __device__ __forceinline__ uint32_t smem_u32(const void* p) {
    uint32_t a;
    asm("{ .reg .u64 t; cvta.to.shared.u64 t, %1; cvt.u32.u64 %0, t; }" : "=r"(a) : "l"(p));
    return a;
}
static __device__ __forceinline__ uint32_t h2_as_u32(__half2 h) {
    uint32_t u;
    memcpy(&u, &h, 4);
    return u;
}
static __device__ __forceinline__ float tanh_fast(float x) {
    float r;
    asm("tanh.approx.f32 %0, %1;" : "=f"(r) : "f"(x));
    return r;
}
static __device__ __forceinline__ void ldmat4(uint32_t* r, uint32_t addr) {
    asm volatile("ldmatrix.sync.aligned.m8n8.x4.shared.b16 {%0,%1,%2,%3}, [%4];"
                 : "=r"(r[0]), "=r"(r[1]), "=r"(r[2]), "=r"(r[3]) : "r"(addr));
}
static __device__ __forceinline__ void mma16816(float* c, const uint32_t* a,
                                                uint32_t b0, uint32_t b1) {
    asm volatile(
        "mma.sync.aligned.m16n8k16.row.col.f32.f16.f16.f32 "
        "{%0,%1,%2,%3}, {%4,%5,%6,%7}, {%8,%9}, {%0,%1,%2,%3};"
        : "+f"(c[0]), "+f"(c[1]), "+f"(c[2]), "+f"(c[3])
        : "r"(a[0]), "r"(a[1]), "r"(a[2]), "r"(a[3]), "r"(b0), "r"(b1));
}
static __device__ __forceinline__ void cp16(uint32_t dst, const void* src) {
    asm volatile("cp.async.cg.shared.global [%0], [%1], 16;" :: "r"(dst), "l"(src));
}
#define CP_COMMIT() asm volatile("cp.async.commit_group;" ::: "memory")
#define CP_WAIT0()  asm volatile("cp.async.wait_group 0;" ::: "memory")
#define CP_WAIT1()  asm volatile("cp.async.wait_group 1;" ::: "memory")

static __device__ __forceinline__ void issue_slab(uint32_t smb_slab,
                                                  const unsigned char* src, int tid) {
    #pragma unroll
    for (int i = 0; i < 4; ++i)
        cp16(smb_slab + tid * 16 + i * 8192, src + tid * 16 + i * 8192);
    CP_COMMIT();
}

// -------- weight prep: fragment-order fp16 pack --------
// b-frag (m16n8k16 col): reg0 = B[2q+{0,1}][lane/4], reg1 = B[2q+8+{0,1}][lane/4], q=lane%4
__global__ void prep_weights(const float* __restrict__ W2, const float* __restrict__ W3) {
    int idx = blockIdx.x * blockDim.x + threadIdx.x;
    if (idx < 262144) {
        int k = idx >> 9, n = idx & 511;
        __half h = __float2half_rn(W2[k * 512 + n]);
        int nc = n >> 7, sl = k >> 7, ks = (k >> 4) & 7, reg = (k >> 3) & 1;
        int q = (k >> 1) & 3, hf = k & 1;
        int wn = (n >> 5) & 3, tn = (n >> 3) & 3, lane = ((n & 7) << 2) | q;
        uint32_t off = (uint32_t)nc * 131072 + sl * 32768 + ks * 4096 + wn * 1024
                     + lane * 32 + tn * 8 + reg * 4 + hf * 2;
        *(__half*)(g_WF2 + off) = h;
    } else if (idx < 262144 + 131072) {
        int j = idx - 262144;
        int k = j >> 8, n = j & 255;
        __half h = __float2half_rn(W3[k * 256 + n]);
        int nc = n >> 7, sl = k >> 7, ks = (k >> 4) & 7, reg = (k >> 3) & 1;
        int q = (k >> 1) & 3, hf = k & 1;
        int wn = (n >> 5) & 3, tn = (n >> 3) & 3, lane = ((n & 7) << 2) | q;
        uint32_t off = (uint32_t)nc * 131072 + sl * 32768 + ks * 4096 + wn * 1024
                     + lane * 32 + tn * 8 + reg * 4 + hf * 2;
        *(__half*)(g_WF3 + off) = h;
    }
}

// ------------------------------- main kernel -------------------------------
__global__ void __launch_bounds__(NT, 1)
node_rk4_hmma(const float* __restrict__ y0, const float* __restrict__ tp,
              const float* __restrict__ W1, const float* __restrict__ b1,
              const float* __restrict__ b2, const float* __restrict__ b3,
              const float* __restrict__ W4, const float* __restrict__ b4,
              float* __restrict__ out, int Brows, int T)
{
    extern __shared__ char sm[];
    const uint32_t smb = smem_u32(sm);
    const int tid  = threadIdx.x;
    const int wid  = tid >> 5;
    const int lane = tid & 31;
    const int wm   = wid & 3;        // m-warp (0..3)
    const int wn   = wid >> 2;       // n-warp (0..3)
    const int base = blockIdx.x * MROWS;

    float* W1s = (float*)(sm + SM_W1);
    float* b1s = (float*)(sm + SM_B1);
    float* b2s = (float*)(sm + SM_B2);
    float* b3s = (float*)(sm + SM_B3);
    float* W4s = (float*)(sm + SM_W4);
    float* b4s = (float*)(sm + SM_B4);
    float* red = (float*)(sm + SM_RED);
    float* ycur   = (float*)(sm + SM_YC);
    float* ystage = (float*)(sm + SM_YS);
    float* ysum   = (float*)(sm + SM_YSUM);

    for (int i = tid; i < 1024; i += NT) W1s[i] = W1[i];
    if (tid < 512) b1s[tid] = b1[tid];
    if (tid < 512) b2s[tid] = b2[tid];
    if (tid < 256) b3s[tid] = b3[tid];
    if (tid < 512) W4s[tid] = W4[tid];
    if (tid < 2)   b4s[tid] = b4[tid];

    if (tid < MROWS * 2) {
        int r = tid >> 1, c = tid & 1;
        long g = (long)base + r;
        float v = (g < Brows) ? y0[g * 2 + c] : 0.0f;
        ycur[tid] = v;
        if (g < Brows) out[g * 2 + c] = v;
    }
    __syncthreads();

    // ldmatrix lane addressing constants (per warp, per tm-tile)
    const int lrow = lane & 15;
    const uint32_t lkoff = (uint32_t)(lane >> 4) << 4;
    const int q4 = lane & 3;          // t%4
    const int r4 = lane >> 2;         // t/4

    #pragma unroll 1
    for (int s = 0; s < T - 1; ++s) {
        const float dt = tp[s + 1] - tp[s];

        #pragma unroll 1
        for (int stage = 0; stage < 4; ++stage) {
            const float* yin = (stage == 0) ? ycur : ystage;

            // prefetch layer-2 slab 0 (overlaps layer-1 compute)
            issue_slab(smb + SM_SLAB, g_WF2, tid);

            // ===== layer 1 (2 -> 512): FFMA + tanh -> fp16 A tile =====
            {
                const int r = tid >> 2, q = tid & 3;
                const float a0 = yin[r * 2 + 0];
                const float a1 = yin[r * 2 + 1];
                char* arow = sm + SM_A + r * ASTR;
                #pragma unroll 8
                for (int j = 0; j < 64; ++j) {
                    const int c = 2 * q + 8 * j;
                    float v0 = tanh_fast(fmaf(a0, W1s[c],     fmaf(a1, W1s[512 + c],     b1s[c])));
                    float v1 = tanh_fast(fmaf(a0, W1s[c + 1], fmaf(a1, W1s[512 + c + 1], b1s[c + 1])));
                    *(__half2*)(arow + c * 2) = __floats2half2_rn(v0, v1);
                }
            }
            __syncthreads();

            // ===== layer 2 (512 -> 512): HMMA, 4 N-chunks, out staged in regs =====
            uint32_t outh[64];
            #pragma unroll
            for (int nc = 0; nc < 4; ++nc) {
                float acc[2][4][4];
                #pragma unroll
                for (int tm = 0; tm < 2; ++tm)
                    #pragma unroll
                    for (int tn = 0; tn < 4; ++tn)
                        #pragma unroll
                        for (int e = 0; e < 4; ++e) acc[tm][tn][e] = 0.0f;

                #pragma unroll 1
                for (int sl = 0; sl < 4; ++sl) {
                    const int lin = nc * 4 + sl;
                    if (lin < 15) {
                        issue_slab(smb + SM_SLAB + ((lin + 1) & 1) * 32768,
                                   g_WF2 + (size_t)(lin + 1) * 32768, tid);
                        CP_WAIT1();
                    } else {
                        CP_WAIT0();
                    }
                    __syncthreads();
                    const char* slab = sm + SM_SLAB + (lin & 1) * 32768;
                    #pragma unroll
                    for (int ks = 0; ks < 8; ++ks) {
                        const int kstep = sl * 8 + ks;
                        uint32_t a[2][4];
                        #pragma unroll
                        for (int tm = 0; tm < 2; ++tm) {
                            const int arow = wm * 32 + tm * 16 + lrow;
                            ldmat4(a[tm], smb + SM_A + arow * ASTR
                                          + (uint32_t)kstep * 32 + lkoff);
                        }
                        const uint4* bp = (const uint4*)(slab + ks * 4096 + wn * 1024 + lane * 32);
                        const uint4 v0 = bp[0], v1 = bp[1];
                        const uint32_t b00[2] = {v0.x, v0.y}, b01[2] = {v0.z, v0.w};
                        const uint32_t b10[2] = {v1.x, v1.y}, b11[2] = {v1.z, v1.w};
                        #pragma unroll
                        for (int tm = 0; tm < 2; ++tm) {
                            mma16816(acc[tm][0], a[tm], b00[0], b00[1]);
                            mma16816(acc[tm][1], a[tm], b01[0], b01[1]);
                            mma16816(acc[tm][2], a[tm], b10[0], b10[1]);
                            mma16816(acc[tm][3], a[tm], b11[0], b11[1]);
                        }
                    }
                    __syncthreads();
                }
                // chunk epilogue -> registers (half2)
                #pragma unroll
                for (int tm = 0; tm < 2; ++tm)
                    #pragma unroll
                    for (int tn = 0; tn < 4; ++tn) {
                        const int col = nc * 128 + wn * 32 + tn * 8 + 2 * q4;
                        const float bb0 = b2s[col], bb1 = b2s[col + 1];
                        float f0 = tanh_fast(acc[tm][tn][0] + bb0);
                        float f1 = tanh_fast(acc[tm][tn][1] + bb1);
                        float f2 = tanh_fast(acc[tm][tn][2] + bb0);
                        float f3 = tanh_fast(acc[tm][tn][3] + bb1);
                        outh[nc * 16 + tm * 8 + tn * 2 + 0] = h2_as_u32(__floats2half2_rn(f0, f1));
                        outh[nc * 16 + tm * 8 + tn * 2 + 1] = h2_as_u32(__floats2half2_rn(f2, f3));
                    }
            }
            // all A reads done (sync at end of last slab) -> write new A
            #pragma unroll
            for (int nc = 0; nc < 4; ++nc)
                #pragma unroll
                for (int tm = 0; tm < 2; ++tm)
                    #pragma unroll
                    for (int tn = 0; tn < 4; ++tn) {
                        const int col = nc * 128 + wn * 32 + tn * 8 + 2 * q4;
                        const int row = wm * 32 + tm * 16 + r4;
                        *(uint32_t*)(sm + SM_A + row * ASTR + col * 2) =
                            outh[nc * 16 + tm * 8 + tn * 2 + 0];
                        *(uint32_t*)(sm + SM_A + (row + 8) * ASTR + col * 2) =
                            outh[nc * 16 + tm * 8 + tn * 2 + 1];
                    }
            __syncthreads();

            // ===== layer 3 (512 -> 256): HMMA, 2 N-chunks, fused layer 4 =====
            issue_slab(smb + SM_SLAB, g_WF3, tid);
            float p[2][2][2];
            #pragma unroll
            for (int tm = 0; tm < 2; ++tm)
                #pragma unroll
                for (int h = 0; h < 2; ++h) { p[tm][h][0] = 0.0f; p[tm][h][1] = 0.0f; }

            #pragma unroll
            for (int nc = 0; nc < 2; ++nc) {
                float acc[2][4][4];
                #pragma unroll
                for (int tm = 0; tm < 2; ++tm)
                    #pragma unroll
                    for (int tn = 0; tn < 4; ++tn)
                        #pragma unroll
                        for (int e = 0; e < 4; ++e) acc[tm][tn][e] = 0.0f;

                #pragma unroll 1
                for (int sl = 0; sl < 4; ++sl) {
                    const int lin = nc * 4 + sl;
                    if (lin < 7) {
                        issue_slab(smb + SM_SLAB + ((lin + 1) & 1) * 32768,
                                   g_WF3 + (size_t)(lin + 1) * 32768, tid);
                        CP_WAIT1();
                    } else {
                        CP_WAIT0();
                    }
                    __syncthreads();
                    const char* slab = sm + SM_SLAB + (lin & 1) * 32768;
                    #pragma unroll
                    for (int ks = 0; ks < 8; ++ks) {
                        const int kstep = sl * 8 + ks;
                        uint32_t a[2][4];
                        #pragma unroll
                        for (int tm = 0; tm < 2; ++tm) {
                            const int arow = wm * 32 + tm * 16 + lrow;
                            ldmat4(a[tm], smb + SM_A + arow * ASTR
                                          + (uint32_t)kstep * 32 + lkoff);
                        }
                        const uint4* bp = (const uint4*)(slab + ks * 4096 + wn * 1024 + lane * 32);
                        const uint4 v0 = bp[0], v1 = bp[1];
                        const uint32_t b00[2] = {v0.x, v0.y}, b01[2] = {v0.z, v0.w};
                        const uint32_t b10[2] = {v1.x, v1.y}, b11[2] = {v1.z, v1.w};
                        #pragma unroll
                        for (int tm = 0; tm < 2; ++tm) {
                            mma16816(acc[tm][0], a[tm], b00[0], b00[1]);
                            mma16816(acc[tm][1], a[tm], b01[0], b01[1]);
                            mma16816(acc[tm][2], a[tm], b10[0], b10[1]);
                            mma16816(acc[tm][3], a[tm], b11[0], b11[1]);
                        }
                    }
                    __syncthreads();
                }
                // chunk epilogue: tanh + layer-4 partial dot products
                #pragma unroll
                for (int tm = 0; tm < 2; ++tm)
                    #pragma unroll
                    for (int tn = 0; tn < 4; ++tn) {
                        const int col = nc * 128 + wn * 32 + tn * 8 + 2 * q4;
                        const float bb0 = b3s[col], bb1 = b3s[col + 1];
                        const float w00 = W4s[col * 2],     w01 = W4s[col * 2 + 1];
                        const float w10 = W4s[col * 2 + 2], w11 = W4s[col * 2 + 3];
                        float h00 = tanh_fast(acc[tm][tn][0] + bb0);
                        float h01 = tanh_fast(acc[tm][tn][1] + bb1);
                        float h10 = tanh_fast(acc[tm][tn][2] + bb0);
                        float h11 = tanh_fast(acc[tm][tn][3] + bb1);
                        p[tm][0][0] = fmaf(h00, w00, fmaf(h01, w10, p[tm][0][0]));
                        p[tm][0][1] = fmaf(h00, w01, fmaf(h01, w11, p[tm][0][1]));
                        p[tm][1][0] = fmaf(h10, w00, fmaf(h11, w10, p[tm][1][0]));
                        p[tm][1][1] = fmaf(h10, w01, fmaf(h11, w11, p[tm][1][1]));
                    }
            }
            // quad reduction (lanes sharing t/4 hold same rows)
            #pragma unroll
            for (int off = 1; off <= 2; off <<= 1)
                #pragma unroll
                for (int tm = 0; tm < 2; ++tm)
                    #pragma unroll
                    for (int h = 0; h < 2; ++h) {
                        p[tm][h][0] += __shfl_xor_sync(0xFFFFFFFF, p[tm][h][0], off);
                        p[tm][h][1] += __shfl_xor_sync(0xFFFFFFFF, p[tm][h][1], off);
                    }
            if (q4 == 0) {
                #pragma unroll
                for (int tm = 0; tm < 2; ++tm)
                    #pragma unroll
                    for (int h = 0; h < 2; ++h) {
                        const int row = wm * 32 + tm * 16 + r4 + 8 * h;
                        red[row * 8 + wn * 2 + 0] = p[tm][h][0];
                        red[row * 8 + wn * 2 + 1] = p[tm][h][1];
                    }
            }
            __syncthreads();

            // ===== RK4 state update =====
            if (tid < MROWS * 2) {
                const int r = tid >> 1, cm = tid & 1;
                const float f = b4s[cm]
                    + red[r * 8 + cm]     + red[r * 8 + 2 + cm]
                    + red[r * 8 + 4 + cm] + red[r * 8 + 6 + cm];
                if (stage == 0) {
                    ysum[tid]   = f;
                    ystage[tid] = fmaf(0.5f * dt, f, ycur[tid]);
                } else if (stage == 1) {
                    ysum[tid]  += 2.0f * f;
                    ystage[tid] = fmaf(0.5f * dt, f, ycur[tid]);
                } else if (stage == 2) {
                    ysum[tid]  += 2.0f * f;
                    ystage[tid] = fmaf(dt, f, ycur[tid]);
                } else {
                    const float yn = fmaf(dt * (1.0f / 6.0f), ysum[tid] + f, ycur[tid]);
                    ycur[tid] = yn;
                    long g = (long)base + r;
                    if (g < Brows)
                        out[(size_t)(s + 1) * Brows * 2 + g * 2 + cm] = yn;
                }
            }
            __syncthreads();
        }
    }
}

extern "C" void kernel_launch(void* const* d_in, const int* in_sizes, int n_in,
                              void* d_out, int out_size) {
    const float* y0 = (const float*)d_in[0];
    const float* tp = (const float*)d_in[1];
    const float* W1 = (const float*)d_in[2];
    const float* b1 = (const float*)d_in[3];
    const float* W2 = (const float*)d_in[4];
    const float* b2 = (const float*)d_in[5];
    const float* W3 = (const float*)d_in[6];
    const float* b3 = (const float*)d_in[7];
    const float* W4 = (const float*)d_in[8];
    const float* b4 = (const float*)d_in[9];
    float* out = (float*)d_out;

    const int B = in_sizes[0] / 2;   // 65536
    const int T = in_sizes[1];       // 100

    prep_weights<<<1536, 256>>>(W2, W3);

    cudaFuncSetAttribute(node_rk4_hmma,
                         cudaFuncAttributeMaxDynamicSharedMemorySize, SM_TOTAL);
    const int grid = (B + MROWS - 1) / MROWS;
    node_rk4_hmma<<<grid, NT, SM_TOTAL>>>(y0, tp, W1, b1, b2, b3, W4, b4, out, B, T);
}

// round 12
// speedup vs baseline: 16.1013x; 1.0002x over previous
#include <cuda_runtime.h>
#include <cuda_fp16.h>
#include <stdint.h>
#include <string.h>

#define NT     512
#define MROWS  128
#define ASTR   1040      // bytes per padded A row (520 halfs)

// Fragment-ordered fp16 weights:
// layout: [nc][slab(128k)][ks(8)][wn(4)][lane(32)][tn(4)][reg(2)][half(2)]
__device__ __align__(16) unsigned char g_WF2[524288];   // W2: nc=4
__device__ __align__(16) unsigned char g_WF3[262144];   // W3: nc=2

// ---------------- smem layout (bytes) ----------------
#define SM_A     0                         // 128*1040 = 133120
#define SM_SLAB  133120                    // 2 x 32768
#define SM_W1    (SM_SLAB + 65536)         // 1024 f32
#define SM_B1    (SM_W1 + 4096)            // 512 f32
#define SM_B2    (SM_B1 + 2048)            // 512 f32
#define SM_B3    (SM_B2 + 2048)            // 256 f32
#define SM_W4    (SM_B3 + 1024)            // 512 f32
#define SM_B4    (SM_W4 + 2048)            // 2 f32 (+pad)
#define SM_RED   (SM_B4 + 16)              // 128*4*2 f32
#define SM_YC    (SM_RED + 4096)
#define SM_YS    (SM_YC + 1024)
#define SM_YSUM  (SM_YS + 1024)
#define SM_TOTAL (SM_YSUM + 1024)          // 217104

static __device__ __forceinline__ uint32_t smem_u32(const void* p) {
    uint32_t a;
    asm("{ .reg .u64 t; cvta.to.shared.u64 t, %1; cvt.u32.u64 %0, t; }" : "=r"(a) : "l"(p));
    return a;
}
static __device__ __forceinline__ uint32_t h2_as_u32(__half2 h) {
    uint32_t u;
    memcpy(&u, &h, 4);
    return u;
}
static __device__ __forceinline__ float tanh_fast(float x) {
    float r;
    asm("tanh.approx.f32 %0, %1;" : "=f"(r) : "f"(x));
    return r;
}
static __device__ __forceinline__ void ldmat4(uint32_t* r, uint32_t addr) {
    asm volatile("ldmatrix.sync.aligned.m8n8.x4.shared.b16 {%0,%1,%2,%3}, [%4];"
                 : "=r"(r[0]), "=r"(r[1]), "=r"(r[2]), "=r"(r[3]) : "r"(addr));
}
static __device__ __forceinline__ void mma16816(float* c, const uint32_t* a,
                                                uint32_t b0, uint32_t b1) {
    asm volatile(
        "mma.sync.aligned.m16n8k16.row.col.f32.f16.f16.f32 "
        "{%0,%1,%2,%3}, {%4,%5,%6,%7}, {%8,%9}, {%0,%1,%2,%3};"
        : "+f"(c[0]), "+f"(c[1]), "+f"(c[2]), "+f"(c[3])
        : "r"(a[0]), "r"(a[1]), "r"(a[2]), "r"(a[3]), "r"(b0), "r"(b1));
}
static __device__ __forceinline__ void cp16(uint32_t dst, const void* src) {
    asm volatile("cp.async.cg.shared.global [%0], [%1], 16;" :: "r"(dst), "l"(src));
}
#define CP_COMMIT() asm volatile("cp.async.commit_group;" ::: "memory")
#define CP_WAIT0()  asm volatile("cp.async.wait_group 0;" ::: "memory")
#define CP_WAIT1()  asm volatile("cp.async.wait_group 1;" ::: "memory")

static __device__ __forceinline__ void issue_slab(uint32_t smb_slab,
                                                  const unsigned char* src, int tid) {
    #pragma unroll
    for (int i = 0; i < 4; ++i)
        cp16(smb_slab + tid * 16 + i * 8192, src + tid * 16 + i * 8192);
    CP_COMMIT();
}

// -------- weight prep: fragment-order fp16 pack --------
// b-frag (m16n8k16 col): reg0 = B[2q+{0,1}][lane/4], reg1 = B[2q+8+{0,1}][lane/4], q=lane%4
__global__ void prep_weights(const float* __restrict__ W2, const float* __restrict__ W3) {
    int idx = blockIdx.x * blockDim.x + threadIdx.x;
    if (idx < 262144) {
        int k = idx >> 9, n = idx & 511;
        __half h = __float2half_rn(W2[k * 512 + n]);
        int nc = n >> 7, sl = k >> 7, ks = (k >> 4) & 7, reg = (k >> 3) & 1;
        int q = (k >> 1) & 3, hf = k & 1;
        int wn = (n >> 5) & 3, tn = (n >> 3) & 3, lane = ((n & 7) << 2) | q;
        uint32_t off = (uint32_t)nc * 131072 + sl * 32768 + ks * 4096 + wn * 1024
                     + lane * 32 + tn * 8 + reg * 4 + hf * 2;
        *(__half*)(g_WF2 + off) = h;
    } else if (idx < 262144 + 131072) {
        int j = idx - 262144;
        int k = j >> 8, n = j & 255;
        __half h = __float2half_rn(W3[k * 256 + n]);
        int nc = n >> 7, sl = k >> 7, ks = (k >> 4) & 7, reg = (k >> 3) & 1;
        int q = (k >> 1) & 3, hf = k & 1;
        int wn = (n >> 5) & 3, tn = (n >> 3) & 3, lane = ((n & 7) << 2) | q;
        uint32_t off = (uint32_t)nc * 131072 + sl * 32768 + ks * 4096 + wn * 1024
                     + lane * 32 + tn * 8 + reg * 4 + hf * 2;
        *(__half*)(g_WF3 + off) = h;
    }
}

// ------------------------------- main kernel -------------------------------
__global__ void __launch_bounds__(NT, 1)
node_rk4_hmma(const float* __restrict__ y0, const float* __restrict__ tp,
              const float* __restrict__ W1, const float* __restrict__ b1,
              const float* __restrict__ b2, const float* __restrict__ b3,
              const float* __restrict__ W4, const float* __restrict__ b4,
              float* __restrict__ out, int Brows, int T)
{
    extern __shared__ char sm[];
    const uint32_t smb = smem_u32(sm);
    const int tid  = threadIdx.x;
    const int wid  = tid >> 5;
    const int lane = tid & 31;
    const int wm   = wid & 3;        // m-warp (0..3)
    const int wn   = wid >> 2;       // n-warp (0..3)
    const int base = blockIdx.x * MROWS;

    float* W1s = (float*)(sm + SM_W1);
    float* b1s = (float*)(sm + SM_B1);
    float* b2s = (float*)(sm + SM_B2);
    float* b3s = (float*)(sm + SM_B3);
    float* W4s = (float*)(sm + SM_W4);
    float* b4s = (float*)(sm + SM_B4);
    float* red = (float*)(sm + SM_RED);
    float* ycur   = (float*)(sm + SM_YC);
    float* ystage = (float*)(sm + SM_YS);
    float* ysum   = (float*)(sm + SM_YSUM);

    for (int i = tid; i < 1024; i += NT) W1s[i] = W1[i];
    if (tid < 512) b1s[tid] = b1[tid];
    if (tid < 512) b2s[tid] = b2[tid];
    if (tid < 256) b3s[tid] = b3[tid];
    if (tid < 512) W4s[tid] = W4[tid];
    if (tid < 2)   b4s[tid] = b4[tid];

    if (tid < MROWS * 2) {
        int r = tid >> 1, c = tid & 1;
        long g = (long)base + r;
        float v = (g < Brows) ? y0[g * 2 + c] : 0.0f;
        ycur[tid] = v;
        if (g < Brows) out[g * 2 + c] = v;
    }
    __syncthreads();

    // ldmatrix lane addressing constants (per warp, per tm-tile)
    const int lrow = lane & 15;
    const uint32_t lkoff = (uint32_t)(lane >> 4) << 4;
    const int q4 = lane & 3;          // t%4
    const int r4 = lane >> 2;         // t/4

    #pragma unroll 1
    for (int s = 0; s < T - 1; ++s) {
        const float dt = tp[s + 1] - tp[s];

        #pragma unroll 1
        for (int stage = 0; stage < 4; ++stage) {
            const float* yin = (stage == 0) ? ycur : ystage;

            // prefetch layer-2 slab 0 (overlaps layer-1 compute)
            issue_slab(smb + SM_SLAB, g_WF2, tid);

            // ===== layer 1 (2 -> 512): FFMA + tanh -> fp16 A tile =====
            {
                const int r = tid >> 2, q = tid & 3;
                const float a0 = yin[r * 2 + 0];
                const float a1 = yin[r * 2 + 1];
                char* arow = sm + SM_A + r * ASTR;
                #pragma unroll 8
                for (int j = 0; j < 64; ++j) {
                    const int c = 2 * q + 8 * j;
                    float v0 = tanh_fast(fmaf(a0, W1s[c],     fmaf(a1, W1s[512 + c],     b1s[c])));
                    float v1 = tanh_fast(fmaf(a0, W1s[c + 1], fmaf(a1, W1s[512 + c + 1], b1s[c + 1])));
                    *(__half2*)(arow + c * 2) = __floats2half2_rn(v0, v1);
                }
            }
            __syncthreads();

            // ===== layer 2 (512 -> 512): HMMA, 4 N-chunks, out staged in regs =====
            uint32_t outh[64];
            #pragma unroll
            for (int nc = 0; nc < 4; ++nc) {
                float acc[2][4][4];
                #pragma unroll
                for (int tm = 0; tm < 2; ++tm)
                    #pragma unroll
                    for (int tn = 0; tn < 4; ++tn)
                        #pragma unroll
                        for (int e = 0; e < 4; ++e) acc[tm][tn][e] = 0.0f;

                #pragma unroll 1
                for (int sl = 0; sl < 4; ++sl) {
                    const int lin = nc * 4 + sl;
                    if (lin < 15) {
                        issue_slab(smb + SM_SLAB + ((lin + 1) & 1) * 32768,
                                   g_WF2 + (size_t)(lin + 1) * 32768, tid);
                        CP_WAIT1();
                    } else {
                        CP_WAIT0();
                    }
                    __syncthreads();
                    const char* slab = sm + SM_SLAB + (lin & 1) * 32768;
                    #pragma unroll
                    for (int ks = 0; ks < 8; ++ks) {
                        const int kstep = sl * 8 + ks;
                        uint32_t a[2][4];
                        #pragma unroll
                        for (int tm = 0; tm < 2; ++tm) {
                            const int arow = wm * 32 + tm * 16 + lrow;
                            ldmat4(a[tm], smb + SM_A + arow * ASTR
                                          + (uint32_t)kstep * 32 + lkoff);
                        }
                        const uint4* bp = (const uint4*)(slab + ks * 4096 + wn * 1024 + lane * 32);
                        const uint4 v0 = bp[0], v1 = bp[1];
                        const uint32_t b00[2] = {v0.x, v0.y}, b01[2] = {v0.z, v0.w};
                        const uint32_t b10[2] = {v1.x, v1.y}, b11[2] = {v1.z, v1.w};
                        #pragma unroll
                        for (int tm = 0; tm < 2; ++tm) {
                            mma16816(acc[tm][0], a[tm], b00[0], b00[1]);
                            mma16816(acc[tm][1], a[tm], b01[0], b01[1]);
                            mma16816(acc[tm][2], a[tm], b10[0], b10[1]);
                            mma16816(acc[tm][3], a[tm], b11[0], b11[1]);
                        }
                    }
                    __syncthreads();
                }
                // chunk epilogue -> registers (half2)
                #pragma unroll
                for (int tm = 0; tm < 2; ++tm)
                    #pragma unroll
                    for (int tn = 0; tn < 4; ++tn) {
                        const int col = nc * 128 + wn * 32 + tn * 8 + 2 * q4;
                        const float bb0 = b2s[col], bb1 = b2s[col + 1];
                        float f0 = tanh_fast(acc[tm][tn][0] + bb0);
                        float f1 = tanh_fast(acc[tm][tn][1] + bb1);
                        float f2 = tanh_fast(acc[tm][tn][2] + bb0);
                        float f3 = tanh_fast(acc[tm][tn][3] + bb1);
                        outh[nc * 16 + tm * 8 + tn * 2 + 0] = h2_as_u32(__floats2half2_rn(f0, f1));
                        outh[nc * 16 + tm * 8 + tn * 2 + 1] = h2_as_u32(__floats2half2_rn(f2, f3));
                    }
            }
            // all A reads done (sync at end of last slab) -> write new A
            #pragma unroll
            for (int nc = 0; nc < 4; ++nc)
                #pragma unroll
                for (int tm = 0; tm < 2; ++tm)
                    #pragma unroll
                    for (int tn = 0; tn < 4; ++tn) {
                        const int col = nc * 128 + wn * 32 + tn * 8 + 2 * q4;
                        const int row = wm * 32 + tm * 16 + r4;
                        *(uint32_t*)(sm + SM_A + row * ASTR + col * 2) =
                            outh[nc * 16 + tm * 8 + tn * 2 + 0];
                        *(uint32_t*)(sm + SM_A + (row + 8) * ASTR + col * 2) =
                            outh[nc * 16 + tm * 8 + tn * 2 + 1];
                    }
            __syncthreads();

            // ===== layer 3 (512 -> 256): HMMA, 2 N-chunks, fused layer 4 =====
            issue_slab(smb + SM_SLAB, g_WF3, tid);
            float p[2][2][2];
            #pragma unroll
            for (int tm = 0; tm < 2; ++tm)
                #pragma unroll
                for (int h = 0; h < 2; ++h) { p[tm][h][0] = 0.0f; p[tm][h][1] = 0.0f; }

            #pragma unroll
            for (int nc = 0; nc < 2; ++nc) {
                float acc[2][4][4];
                #pragma unroll
                for (int tm = 0; tm < 2; ++tm)
                    #pragma unroll
                    for (int tn = 0; tn < 4; ++tn)
                        #pragma unroll
                        for (int e = 0; e < 4; ++e) acc[tm][tn][e] = 0.0f;

                #pragma unroll 1
                for (int sl = 0; sl < 4; ++sl) {
                    const int lin = nc * 4 + sl;
                    if (lin < 7) {
                        issue_slab(smb + SM_SLAB + ((lin + 1) & 1) * 32768,
                                   g_WF3 + (size_t)(lin + 1) * 32768, tid);
                        CP_WAIT1();
                    } else {
                        CP_WAIT0();
                    }
                    __syncthreads();
                    const char* slab = sm + SM_SLAB + (lin & 1) * 32768;
                    #pragma unroll
                    for (int ks = 0; ks < 8; ++ks) {
                        const int kstep = sl * 8 + ks;
                        uint32_t a[2][4];
                        #pragma unroll
                        for (int tm = 0; tm < 2; ++tm) {
                            const int arow = wm * 32 + tm * 16 + lrow;
                            ldmat4(a[tm], smb + SM_A + arow * ASTR
                                          + (uint32_t)kstep * 32 + lkoff);
                        }
                        const uint4* bp = (const uint4*)(slab + ks * 4096 + wn * 1024 + lane * 32);
                        const uint4 v0 = bp[0], v1 = bp[1];
                        const uint32_t b00[2] = {v0.x, v0.y}, b01[2] = {v0.z, v0.w};
                        const uint32_t b10[2] = {v1.x, v1.y}, b11[2] = {v1.z, v1.w};
                        #pragma unroll
                        for (int tm = 0; tm < 2; ++tm) {
                            mma16816(acc[tm][0], a[tm], b00[0], b00[1]);
                            mma16816(acc[tm][1], a[tm], b01[0], b01[1]);
                            mma16816(acc[tm][2], a[tm], b10[0], b10[1]);
                            mma16816(acc[tm][3], a[tm], b11[0], b11[1]);
                        }
                    }
                    __syncthreads();
                }
                // chunk epilogue: tanh + layer-4 partial dot products
                #pragma unroll
                for (int tm = 0; tm < 2; ++tm)
                    #pragma unroll
                    for (int tn = 0; tn < 4; ++tn) {
                        const int col = nc * 128 + wn * 32 + tn * 8 + 2 * q4;
                        const float bb0 = b3s[col], bb1 = b3s[col + 1];
                        const float w00 = W4s[col * 2],     w01 = W4s[col * 2 + 1];
                        const float w10 = W4s[col * 2 + 2], w11 = W4s[col * 2 + 3];
                        float h00 = tanh_fast(acc[tm][tn][0] + bb0);
                        float h01 = tanh_fast(acc[tm][tn][1] + bb1);
                        float h10 = tanh_fast(acc[tm][tn][2] + bb0);
                        float h11 = tanh_fast(acc[tm][tn][3] + bb1);
                        p[tm][0][0] = fmaf(h00, w00, fmaf(h01, w10, p[tm][0][0]));
                        p[tm][0][1] = fmaf(h00, w01, fmaf(h01, w11, p[tm][0][1]));
                        p[tm][1][0] = fmaf(h10, w00, fmaf(h11, w10, p[tm][1][0]));
                        p[tm][1][1] = fmaf(h10, w01, fmaf(h11, w11, p[tm][1][1]));
                    }
            }
            // quad reduction (lanes sharing t/4 hold same rows)
            #pragma unroll
            for (int off = 1; off <= 2; off <<= 1)
                #pragma unroll
                for (int tm = 0; tm < 2; ++tm)
                    #pragma unroll
                    for (int h = 0; h < 2; ++h) {
                        p[tm][h][0] += __shfl_xor_sync(0xFFFFFFFF, p[tm][h][0], off);
                        p[tm][h][1] += __shfl_xor_sync(0xFFFFFFFF, p[tm][h][1], off);
                    }
            if (q4 == 0) {
                #pragma unroll
                for (int tm = 0; tm < 2; ++tm)
                    #pragma unroll
                    for (int h = 0; h < 2; ++h) {
                        const int row = wm * 32 + tm * 16 + r4 + 8 * h;
                        red[row * 8 + wn * 2 + 0] = p[tm][h][0];
                        red[row * 8 + wn * 2 + 1] = p[tm][h][1];
                    }
            }
            __syncthreads();

            // ===== RK4 state update =====
            if (tid < MROWS * 2) {
                const int r = tid >> 1, cm = tid & 1;
                const float f = b4s[cm]
                    + red[r * 8 + cm]     + red[r * 8 + 2 + cm]
                    + red[r * 8 + 4 + cm] + red[r * 8 + 6 + cm];
                if (stage == 0) {
                    ysum[tid]   = f;
                    ystage[tid] = fmaf(0.5f * dt, f, ycur[tid]);
                } else if (stage == 1) {
                    ysum[tid]  += 2.0f * f;
                    ystage[tid] = fmaf(0.5f * dt, f, ycur[tid]);
                } else if (stage == 2) {
                    ysum[tid]  += 2.0f * f;
                    ystage[tid] = fmaf(dt, f, ycur[tid]);
                } else {
                    const float yn = fmaf(dt * (1.0f / 6.0f), ysum[tid] + f, ycur[tid]);
                    ycur[tid] = yn;
                    long g = (long)base + r;
                    if (g < Brows)
                        out[(size_t)(s + 1) * Brows * 2 + g * 2 + cm] = yn;
                }
            }
            __syncthreads();
        }
    }
}

extern "C" void kernel_launch(void* const* d_in, const int* in_sizes, int n_in,
                              void* d_out, int out_size) {
    const float* y0 = (const float*)d_in[0];
    const float* tp = (const float*)d_in[1];
    const float* W1 = (const float*)d_in[2];
    const float* b1 = (const float*)d_in[3];
    const float* W2 = (const float*)d_in[4];
    const float* b2 = (const float*)d_in[5];
    const float* W3 = (const float*)d_in[6];
    const float* b3 = (const float*)d_in[7];
    const float* W4 = (const float*)d_in[8];
    const float* b4 = (const float*)d_in[9];
    float* out = (float*)d_out;

    const int B = in_sizes[0] / 2;   // 65536
    const int T = in_sizes[1];       // 100

    prep_weights<<<1536, 256>>>(W2, W3);

    cudaFuncSetAttribute(node_rk4_hmma,
                         cudaFuncAttributeMaxDynamicSharedMemorySize, SM_TOTAL);
    const int grid = (B + MROWS - 1) / MROWS;
    node_rk4_hmma<<<grid, NT, SM_TOTAL>>>(y0, tp, W1, b1, b2, b3, W4, b4, out, B, T);
}

// round 13
// speedup vs baseline: 16.1087x; 1.0005x over previous
#include <cuda_runtime.h>
#include <cuda_fp16.h>
#include <stdint.h>
#include <string.h>

#define NT     512
#define MROWS  128
#define ASTR   1040      // bytes per padded A row (520 halfs)

// Fragment-ordered fp16 weights:
// layout: [nc][slab(128k)][ks(8)][wn(4)][lane(32)][tn(4)][reg(2)][half(2)]
__device__ __align__(16) unsigned char g_WF2[524288];   // W2: nc=4
__device__ __align__(16) unsigned char g_WF3[262144];   // W3: nc=2

// ---------------- smem layout (bytes) ----------------
#define SM_A     0                         // 128*1040 = 133120
#define SM_SLAB  133120                    // 2 x 32768
#define SM_W1    (SM_SLAB + 65536)         // 1024 f32
#define SM_B1    (SM_W1 + 4096)            // 512 f32
#define SM_B2    (SM_B1 + 2048)            // 512 f32
#define SM_B3    (SM_B2 + 2048)            // 256 f32
#define SM_W4    (SM_B3 + 1024)            // 512 f32
#define SM_B4    (SM_W4 + 2048)            // 2 f32 (+pad)
#define SM_RED   (SM_B4 + 16)              // 128*4*2 f32
#define SM_YC    (SM_RED + 4096)
#define SM_YS    (SM_YC + 1024)
#define SM_YSUM  (SM_YS + 1024)
#define SM_TOTAL (SM_YSUM + 1024)          // 217104

static __device__ __forceinline__ uint32_t smem_u32(const void* p) {
    uint32_t a;
    asm("{ .reg .u64 t; cvta.to.shared.u64 t, %1; cvt.u32.u64 %0, t; }" : "=r"(a) : "l"(p));
    return a;
}
static __device__ __forceinline__ uint32_t h2_as_u32(__half2 h) {
    uint32_t u;
    memcpy(&u, &h, 4);
    return u;
}
static __device__ __forceinline__ float tanh_fast(float x) {
    float r;
    asm("tanh.approx.f32 %0, %1;" : "=f"(r) : "f"(x));
    return r;
}
static __device__ __forceinline__ void ldmat4(uint32_t* r, uint32_t addr) {
    asm volatile("ldmatrix.sync.aligned.m8n8.x4.shared.b16 {%0,%1,%2,%3}, [%4];"
                 : "=r"(r[0]), "=r"(r[1]), "=r"(r[2]), "=r"(r[3]) : "r"(addr));
}
static __device__ __forceinline__ void mma16816(float* c, const uint32_t* a,
                                                uint32_t b0, uint32_t b1) {
    asm volatile(
        "mma.sync.aligned.m16n8k16.row.col.f32.f16.f16.f32 "
        "{%0,%1,%2,%3}, {%4,%5,%6,%7}, {%8,%9}, {%0,%1,%2,%3};"
        : "+f"(c[0]), "+f"(c[1]), "+f"(c[2]), "+f"(c[3])
        : "r"(a[0]), "r"(a[1]), "r"(a[2]), "r"(a[3]), "r"(b0), "r"(b1));
}
static __device__ __forceinline__ void cp16(uint32_t dst, const void* src) {
    asm volatile("cp.async.cg.shared.global [%0], [%1], 16;" :: "r"(dst), "l"(src));
}
#define CP_COMMIT() asm volatile("cp.async.commit_group;" ::: "memory")
#define CP_WAIT0()  asm volatile("cp.async.wait_group 0;" ::: "memory")
#define CP_WAIT1()  asm volatile("cp.async.wait_group 1;" ::: "memory")

static __device__ __forceinline__ void issue_slab(uint32_t smb_slab,
                                                  const unsigned char* src, int tid) {
    #pragma unroll
    for (int i = 0; i < 4; ++i)
        cp16(smb_slab + tid * 16 + i * 8192, src + tid * 16 + i * 8192);
    CP_COMMIT();
}

// -------- weight prep: fragment-order fp16 pack --------
// b-frag (m16n8k16 col): reg0 = B[2q+{0,1}][lane/4], reg1 = B[2q+8+{0,1}][lane/4], q=lane%4
__global__ void prep_weights(const float* __restrict__ W2, const float* __restrict__ W3) {
    int idx = blockIdx.x * blockDim.x + threadIdx.x;
    if (idx < 262144) {
        int k = idx >> 9, n = idx & 511;
        __half h = __float2half_rn(W2[k * 512 + n]);
        int nc = n >> 7, sl = k >> 7, ks = (k >> 4) & 7, reg = (k >> 3) & 1;
        int q = (k >> 1) & 3, hf = k & 1;
        int wn = (n >> 5) & 3, tn = (n >> 3) & 3, lane = ((n & 7) << 2) | q;
        uint32_t off = (uint32_t)nc * 131072 + sl * 32768 + ks * 4096 + wn * 1024
                     + lane * 32 + tn * 8 + reg * 4 + hf * 2;
        *(__half*)(g_WF2 + off) = h;
    } else if (idx < 262144 + 131072) {
        int j = idx - 262144;
        int k = j >> 8, n = j & 255;
        __half h = __float2half_rn(W3[k * 256 + n]);
        int nc = n >> 7, sl = k >> 7, ks = (k >> 4) & 7, reg = (k >> 3) & 1;
        int q = (k >> 1) & 3, hf = k & 1;
        int wn = (n >> 5) & 3, tn = (n >> 3) & 3, lane = ((n & 7) << 2) | q;
        uint32_t off = (uint32_t)nc * 131072 + sl * 32768 + ks * 4096 + wn * 1024
                     + lane * 32 + tn * 8 + reg * 4 + hf * 2;
        *(__half*)(g_WF3 + off) = h;
    }
}

// ------------------------------- main kernel -------------------------------
__global__ void __launch_bounds__(NT, 1)
node_rk4_hmma(const float* __restrict__ y0, const float* __restrict__ tp,
              const float* __restrict__ W1, const float* __restrict__ b1,
              const float* __restrict__ b2, const float* __restrict__ b3,
              const float* __restrict__ W4, const float* __restrict__ b4,
              float* __restrict__ out, int Brows, int T)
{
    extern __shared__ char sm[];
    const uint32_t smb = smem_u32(sm);
    const int tid  = threadIdx.x;
    const int wid  = tid >> 5;
    const int lane = tid & 31;
    const int wm   = wid & 3;        // m-warp (0..3)
    const int wn   = wid >> 2;       // n-warp (0..3)
    const int base = blockIdx.x * MROWS;

    float* W1s = (float*)(sm + SM_W1);
    float* b1s = (float*)(sm + SM_B1);
    float* b2s = (float*)(sm + SM_B2);
    float* b3s = (float*)(sm + SM_B3);
    float* W4s = (float*)(sm + SM_W4);
    float* b4s = (float*)(sm + SM_B4);
    float* red = (float*)(sm + SM_RED);
    float* ycur   = (float*)(sm + SM_YC);
    float* ystage = (float*)(sm + SM_YS);
    float* ysum   = (float*)(sm + SM_YSUM);

    for (int i = tid; i < 1024; i += NT) W1s[i] = W1[i];
    if (tid < 512) b1s[tid] = b1[tid];
    if (tid < 512) b2s[tid] = b2[tid];
    if (tid < 256) b3s[tid] = b3[tid];
    if (tid < 512) W4s[tid] = W4[tid];
    if (tid < 2)   b4s[tid] = b4[tid];

    if (tid < MROWS * 2) {
        int r = tid >> 1, c = tid & 1;
        long g = (long)base + r;
        float v = (g < Brows) ? y0[g * 2 + c] : 0.0f;
        ycur[tid] = v;
        if (g < Brows) out[g * 2 + c] = v;
    }
    __syncthreads();

    // ldmatrix lane addressing constants (per warp, per tm-tile)
    const int lrow = lane & 15;
    const uint32_t lkoff = (uint32_t)(lane >> 4) << 4;
    const int q4 = lane & 3;          // t%4
    const int r4 = lane >> 2;         // t/4

    #pragma unroll 1
    for (int s = 0; s < T - 1; ++s) {
        const float dt = tp[s + 1] - tp[s];

        #pragma unroll 1
        for (int stage = 0; stage < 4; ++stage) {
            const float* yin = (stage == 0) ? ycur : ystage;

            // prefetch layer-2 slab 0 (overlaps layer-1 compute)
            issue_slab(smb + SM_SLAB, g_WF2, tid);

            // ===== layer 1 (2 -> 512): FFMA + tanh -> fp16 A tile =====
            {
                const int r = tid >> 2, q = tid & 3;
                const float a0 = yin[r * 2 + 0];
                const float a1 = yin[r * 2 + 1];
                char* arow = sm + SM_A + r * ASTR;
                #pragma unroll 8
                for (int j = 0; j < 64; ++j) {
                    const int c = 2 * q + 8 * j;
                    float v0 = tanh_fast(fmaf(a0, W1s[c],     fmaf(a1, W1s[512 + c],     b1s[c])));
                    float v1 = tanh_fast(fmaf(a0, W1s[c + 1], fmaf(a1, W1s[512 + c + 1], b1s[c + 1])));
                    *(__half2*)(arow + c * 2) = __floats2half2_rn(v0, v1);
                }
            }
            __syncthreads();

            // ===== layer 2 (512 -> 512): HMMA, 4 N-chunks, out staged in regs =====
            uint32_t outh[64];
            #pragma unroll
            for (int nc = 0; nc < 4; ++nc) {
                float acc[2][4][4];
                #pragma unroll
                for (int tm = 0; tm < 2; ++tm)
                    #pragma unroll
                    for (int tn = 0; tn < 4; ++tn)
                        #pragma unroll
                        for (int e = 0; e < 4; ++e) acc[tm][tn][e] = 0.0f;

                #pragma unroll 1
                for (int sl = 0; sl < 4; ++sl) {
                    const int lin = nc * 4 + sl;
                    if (lin < 15) {
                        issue_slab(smb + SM_SLAB + ((lin + 1) & 1) * 32768,
                                   g_WF2 + (size_t)(lin + 1) * 32768, tid);
                        CP_WAIT1();
                    } else {
                        CP_WAIT0();
                    }
                    __syncthreads();
                    const char* slab = sm + SM_SLAB + (lin & 1) * 32768;
                    #pragma unroll
                    for (int ks = 0; ks < 8; ++ks) {
                        const int kstep = sl * 8 + ks;
                        uint32_t a[2][4];
                        #pragma unroll
                        for (int tm = 0; tm < 2; ++tm) {
                            const int arow = wm * 32 + tm * 16 + lrow;
                            ldmat4(a[tm], smb + SM_A + arow * ASTR
                                          + (uint32_t)kstep * 32 + lkoff);
                        }
                        const uint4* bp = (const uint4*)(slab + ks * 4096 + wn * 1024 + lane * 32);
                        const uint4 v0 = bp[0], v1 = bp[1];
                        const uint32_t b00[2] = {v0.x, v0.y}, b01[2] = {v0.z, v0.w};
                        const uint32_t b10[2] = {v1.x, v1.y}, b11[2] = {v1.z, v1.w};
                        #pragma unroll
                        for (int tm = 0; tm < 2; ++tm) {
                            mma16816(acc[tm][0], a[tm], b00[0], b00[1]);
                            mma16816(acc[tm][1], a[tm], b01[0], b01[1]);
                            mma16816(acc[tm][2], a[tm], b10[0], b10[1]);
                            mma16816(acc[tm][3], a[tm], b11[0], b11[1]);
                        }
                    }
                    __syncthreads();
                }
                // chunk epilogue -> registers (half2)
                #pragma unroll
                for (int tm = 0; tm < 2; ++tm)
                    #pragma unroll
                    for (int tn = 0; tn < 4; ++tn) {
                        const int col = nc * 128 + wn * 32 + tn * 8 + 2 * q4;
                        const float bb0 = b2s[col], bb1 = b2s[col + 1];
                        float f0 = tanh_fast(acc[tm][tn][0] + bb0);
                        float f1 = tanh_fast(acc[tm][tn][1] + bb1);
                        float f2 = tanh_fast(acc[tm][tn][2] + bb0);
                        float f3 = tanh_fast(acc[tm][tn][3] + bb1);
                        outh[nc * 16 + tm * 8 + tn * 2 + 0] = h2_as_u32(__floats2half2_rn(f0, f1));
                        outh[nc * 16 + tm * 8 + tn * 2 + 1] = h2_as_u32(__floats2half2_rn(f2, f3));
                    }
            }
            // all A reads done (sync at end of last slab) -> write new A
            #pragma unroll
            for (int nc = 0; nc < 4; ++nc)
                #pragma unroll
                for (int tm = 0; tm < 2; ++tm)
                    #pragma unroll
                    for (int tn = 0; tn < 4; ++tn) {
                        const int col = nc * 128 + wn * 32 + tn * 8 + 2 * q4;
                        const int row = wm * 32 + tm * 16 + r4;
                        *(uint32_t*)(sm + SM_A + row * ASTR + col * 2) =
                            outh[nc * 16 + tm * 8 + tn * 2 + 0];
                        *(uint32_t*)(sm + SM_A + (row + 8) * ASTR + col * 2) =
                            outh[nc * 16 + tm * 8 + tn * 2 + 1];
                    }
            __syncthreads();

            // ===== layer 3 (512 -> 256): HMMA, 2 N-chunks, fused layer 4 =====
            issue_slab(smb + SM_SLAB, g_WF3, tid);
            float p[2][2][2];
            #pragma unroll
            for (int tm = 0; tm < 2; ++tm)
                #pragma unroll
                for (int h = 0; h < 2; ++h) { p[tm][h][0] = 0.0f; p[tm][h][1] = 0.0f; }

            #pragma unroll
            for (int nc = 0; nc < 2; ++nc) {
                float acc[2][4][4];
                #pragma unroll
                for (int tm = 0; tm < 2; ++tm)
                    #pragma unroll
                    for (int tn = 0; tn < 4; ++tn)
                        #pragma unroll
                        for (int e = 0; e < 4; ++e) acc[tm][tn][e] = 0.0f;

                #pragma unroll 1
                for (int sl = 0; sl < 4; ++sl) {
                    const int lin = nc * 4 + sl;
                    if (lin < 7) {
                        issue_slab(smb + SM_SLAB + ((lin + 1) & 1) * 32768,
                                   g_WF3 + (size_t)(lin + 1) * 32768, tid);
                        CP_WAIT1();
                    } else {
                        CP_WAIT0();
                    }
                    __syncthreads();
                    const char* slab = sm + SM_SLAB + (lin & 1) * 32768;
                    #pragma unroll
                    for (int ks = 0; ks < 8; ++ks) {
                        const int kstep = sl * 8 + ks;
                        uint32_t a[2][4];
                        #pragma unroll
                        for (int tm = 0; tm < 2; ++tm) {
                            const int arow = wm * 32 + tm * 16 + lrow;
                            ldmat4(a[tm], smb + SM_A + arow * ASTR
                                          + (uint32_t)kstep * 32 + lkoff);
                        }
                        const uint4* bp = (const uint4*)(slab + ks * 4096 + wn * 1024 + lane * 32);
                        const uint4 v0 = bp[0], v1 = bp[1];
                        const uint32_t b00[2] = {v0.x, v0.y}, b01[2] = {v0.z, v0.w};
                        const uint32_t b10[2] = {v1.x, v1.y}, b11[2] = {v1.z, v1.w};
                        #pragma unroll
                        for (int tm = 0; tm < 2; ++tm) {
                            mma16816(acc[tm][0], a[tm], b00[0], b00[1]);
                            mma16816(acc[tm][1], a[tm], b01[0], b01[1]);
                            mma16816(acc[tm][2], a[tm], b10[0], b10[1]);
                            mma16816(acc[tm][3], a[tm], b11[0], b11[1]);
                        }
                    }
                    __syncthreads();
                }
                // chunk epilogue: tanh + layer-4 partial dot products
                #pragma unroll
                for (int tm = 0; tm < 2; ++tm)
                    #pragma unroll
                    for (int tn = 0; tn < 4; ++tn) {
                        const int col = nc * 128 + wn * 32 + tn * 8 + 2 * q4;
                        const float bb0 = b3s[col], bb1 = b3s[col + 1];
                        const float w00 = W4s[col * 2],     w01 = W4s[col * 2 + 1];
                        const float w10 = W4s[col * 2 + 2], w11 = W4s[col * 2 + 3];
                        float h00 = tanh_fast(acc[tm][tn][0] + bb0);
                        float h01 = tanh_fast(acc[tm][tn][1] + bb1);
                        float h10 = tanh_fast(acc[tm][tn][2] + bb0);
                        float h11 = tanh_fast(acc[tm][tn][3] + bb1);
                        p[tm][0][0] = fmaf(h00, w00, fmaf(h01, w10, p[tm][0][0]));
                        p[tm][0][1] = fmaf(h00, w01, fmaf(h01, w11, p[tm][0][1]));
                        p[tm][1][0] = fmaf(h10, w00, fmaf(h11, w10, p[tm][1][0]));
                        p[tm][1][1] = fmaf(h10, w01, fmaf(h11, w11, p[tm][1][1]));
                    }
            }
            // quad reduction (lanes sharing t/4 hold same rows)
            #pragma unroll
            for (int off = 1; off <= 2; off <<= 1)
                #pragma unroll
                for (int tm = 0; tm < 2; ++tm)
                    #pragma unroll
                    for (int h = 0; h < 2; ++h) {
                        p[tm][h][0] += __shfl_xor_sync(0xFFFFFFFF, p[tm][h][0], off);
                        p[tm][h][1] += __shfl_xor_sync(0xFFFFFFFF, p[tm][h][1], off);
                    }
            if (q4 == 0) {
                #pragma unroll
                for (int tm = 0; tm < 2; ++tm)
                    #pragma unroll
                    for (int h = 0; h < 2; ++h) {
                        const int row = wm * 32 + tm * 16 + r4 + 8 * h;
                        red[row * 8 + wn * 2 + 0] = p[tm][h][0];
                        red[row * 8 + wn * 2 + 1] = p[tm][h][1];
                    }
            }
            __syncthreads();

            // ===== RK4 state update =====
            if (tid < MROWS * 2) {
                const int r = tid >> 1, cm = tid & 1;
                const float f = b4s[cm]
                    + red[r * 8 + cm]     + red[r * 8 + 2 + cm]
                    + red[r * 8 + 4 + cm] + red[r * 8 + 6 + cm];
                if (stage == 0) {
                    ysum[tid]   = f;
                    ystage[tid] = fmaf(0.5f * dt, f, ycur[tid]);
                } else if (stage == 1) {
                    ysum[tid]  += 2.0f * f;
                    ystage[tid] = fmaf(0.5f * dt, f, ycur[tid]);
                } else if (stage == 2) {
                    ysum[tid]  += 2.0f * f;
                    ystage[tid] = fmaf(dt, f, ycur[tid]);
                } else {
                    const float yn = fmaf(dt * (1.0f / 6.0f), ysum[tid] + f, ycur[tid]);
                    ycur[tid] = yn;
                    long g = (long)base + r;
                    if (g < Brows)
                        out[(size_t)(s + 1) * Brows * 2 + g * 2 + cm] = yn;
                }
            }
            __syncthreads();
        }
    }
}

extern "C" void kernel_launch(void* const* d_in, const int* in_sizes, int n_in,
                              void* d_out, int out_size) {
    const float* y0 = (const float*)d_in[0];
    const float* tp = (const float*)d_in[1];
    const float* W1 = (const float*)d_in[2];
    const float* b1 = (const float*)d_in[3];
    const float* W2 = (const float*)d_in[4];
    const float* b2 = (const float*)d_in[5];
    const float* W3 = (const float*)d_in[6];
    const float* b3 = (const float*)d_in[7];
    const float* W4 = (const float*)d_in[8];
    const float* b4 = (const float*)d_in[9];
    float* out = (float*)d_out;

    const int B = in_sizes[0] / 2;   // 65536
    const int T = in_sizes[1];       // 100

    prep_weights<<<1536, 256>>>(W2, W3);

    cudaFuncSetAttribute(node_rk4_hmma,
                         cudaFuncAttributeMaxDynamicSharedMemorySize, SM_TOTAL);
    const int grid = (B + MROWS - 1) / MROWS;
    node_rk4_hmma<<<grid, NT, SM_TOTAL>>>(y0, tp, W1, b1, b2, b3, W4, b4, out, B, T);
}